// round 15
// baseline (speedup 1.0000x reference)
#include <cuda_runtime.h>
#include <cuda_fp16.h>
#include <cstdint>

// Problem constants
#define NPIX     65536      // 256*256
#define NOUT     16384      // 128*128
#define HALF     32768      // pixels per half-plane
#define TPB      1024
#define NSM      148

// L2-resident compressed index table (4 x uint16 per output = 128 KB)
__device__ uint16_t g_idx16[NOUT * 4];

// ---------------------------------------------------------------------------
// Pass 0: compress gather_idx (int64 OR int32, autodetected) -> uint16.
// Vectorized: each thread converts 8 entries. gather_idx is a permutation of
// [0,65536): among 8 sampled entries at most one is zero, so "first 8 odd
// u32 words all zero" <=> int64 layout.
// ---------------------------------------------------------------------------
__global__ void cvt_idx_kernel(const uint32_t* __restrict__ src) {
    const uint4* s4 = reinterpret_cast<const uint4*>(src);
    const uint4 w0 = __ldg(&s4[0]);
    const uint4 w1 = __ldg(&s4[1]);
    const uint4 w2 = __ldg(&s4[2]);
    const uint4 w3 = __ldg(&s4[3]);
    const bool is64 = (w0.y | w0.w | w1.y | w1.w | w2.y | w2.w | w3.y | w3.w) == 0u;

    const int t = blockIdx.x * blockDim.x + threadIdx.x;   // 0 .. 8191
    uint32_t v[8];
    if (is64) {
#pragma unroll
        for (int j = 0; j < 4; j++) {
            const uint4 u = __ldg(&s4[t * 4 + j]);   // two int64 entries
            v[2 * j]     = u.x;
            v[2 * j + 1] = u.z;
        }
    } else {
#pragma unroll
        for (int j = 0; j < 2; j++) {
            const uint4 u = __ldg(&s4[t * 2 + j]);   // four int32 entries
            v[4 * j]     = u.x;
            v[4 * j + 1] = u.y;
            v[4 * j + 2] = u.z;
            v[4 * j + 3] = u.w;
        }
    }
    uint4 o;
    o.x = (v[0] & 0xFFFFu) | (v[1] << 16);
    o.y = (v[2] & 0xFFFFu) | (v[3] << 16);
    o.z = (v[4] & 0xFFFFu) | (v[5] << 16);
    o.w = (v[6] & 0xFFFFu) | (v[7] << 16);
    reinterpret_cast<uint4*>(g_idx16)[t] = o;
}

// ---------------------------------------------------------------------------
// Persistent ring kernel (3 x 64KB fp16 half-plane buffers, 192 KB smem).
// R14 champion + paired-output gather: each gchunk handles TWO adjacent
// outputs with ONE idx LDG.128 and ONE STG.64 (halves idx/store wavefronts).
// Next-plane h0 fill remains software-pipelined through the gather chunks.
// ---------------------------------------------------------------------------
extern __shared__ __half sh[];   // 3 * HALF halves = 192 KB dynamic

__device__ __forceinline__ void gchunk(int k, int t,
                                       const uint4* __restrict__ idx4,
                                       unsigned oA, unsigned oB,
                                       float2* __restrict__ op2) {
    const int u = t + k * TPB;                 // output-pair index 0..8191
    const uint4 q = __ldg(&idx4[u]);
    const unsigned i0 = q.x & 0xFFFFu, i1 = q.x >> 16;
    const unsigned i2 = q.y & 0xFFFFu, i3 = q.y >> 16;
    const unsigned i4 = q.z & 0xFFFFu, i5 = q.z >> 16;
    const unsigned i6 = q.w & 0xFFFFu, i7 = q.w >> 16;
    const __half a0 = sh[((i0 & 0x8000u) ? oB : oA) + (i0 & 0x7FFFu)];
    const __half a1 = sh[((i1 & 0x8000u) ? oB : oA) + (i1 & 0x7FFFu)];
    const __half a2 = sh[((i2 & 0x8000u) ? oB : oA) + (i2 & 0x7FFFu)];
    const __half a3 = sh[((i3 & 0x8000u) ? oB : oA) + (i3 & 0x7FFFu)];
    const __half b0 = sh[((i4 & 0x8000u) ? oB : oA) + (i4 & 0x7FFFu)];
    const __half b1 = sh[((i5 & 0x8000u) ? oB : oA) + (i5 & 0x7FFFu)];
    const __half b2 = sh[((i6 & 0x8000u) ? oB : oA) + (i6 & 0x7FFFu)];
    const __half b3 = sh[((i7 & 0x8000u) ? oB : oA) + (i7 & 0x7FFFu)];
    float2 r;
    r.x = __half2float(__hmax(__hmax(a0, a1), __hmax(a2, a3)));
    r.y = __half2float(__hmax(__hmax(b0, b1), __hmax(b2, b3)));
    __stcs(&op2[u], r);
}

__device__ __forceinline__ void ldg2(const float4* __restrict__ src, int i,
                                     int t, float4& a, float4& b) {
    const int q = t + i * TPB;                 // uint4 dst index 0..4095
    a = __ldcs(&src[2 * q]);
    b = __ldcs(&src[2 * q + 1]);
}

__device__ __forceinline__ void sts2(unsigned ofs, int i, int t,
                                     const float4& a, const float4& b) {
    const __half2 h0 = __floats2half2_rn(a.x, a.y);
    const __half2 h1 = __floats2half2_rn(a.z, a.w);
    const __half2 h2 = __floats2half2_rn(b.x, b.y);
    const __half2 h3 = __floats2half2_rn(b.z, b.w);
    uint4 u;
    u.x = *reinterpret_cast<const unsigned*>(&h0);
    u.y = *reinterpret_cast<const unsigned*>(&h1);
    u.z = *reinterpret_cast<const unsigned*>(&h2);
    u.w = *reinterpret_cast<const unsigned*>(&h3);
    reinterpret_cast<uint4*>(sh + ofs)[t + i * TPB] = u;
}

__device__ __forceinline__ void fill_half(unsigned ofs,
                                          const float4* __restrict__ src,
                                          int t) {
#pragma unroll
    for (int i = 0; i < 4; i++) {
        float4 a, b;
        ldg2(src, i, t, a, b);
        sts2(ofs, i, t, a, b);
    }
}

__global__ void __launch_bounds__(TPB, 1)
pool_kernel(const float* __restrict__ x, float* __restrict__ out, int planes) {
    const int t = threadIdx.x;
    int p = blockIdx.x;

    const uint4* __restrict__ idx4 =
        reinterpret_cast<const uint4*>(g_idx16);  // one uint4 = 2 outputs

    unsigned oA = 0, oB = HALF, oC = 2 * HALF;    // ring offsets (half units)

    // Prologue: fill h0 -> A, h1 -> B of the first plane.
    {
        const float4* xp = reinterpret_cast<const float4*>(x + (size_t)p * NPIX);
        fill_half(oA, xp, t);
        fill_half(oB, xp + HALF / 4, t);
    }
    __syncthreads();

    while (true) {
        const int pn = p + (int)gridDim.x;
        const bool have = pn < planes;
        const float* nx = x + (size_t)pn * NPIX;
        const float4* nxp = reinterpret_cast<const float4*>(nx);
        float2* __restrict__ op2 =
            reinterpret_cast<float2*>(out + (size_t)p * NOUT);

        float4 a0, b0, a1, b1;

        // ---- gather p (8 paired chunks), next h0 fill pipelined through ----
        if (have) ldg2(nxp, 0, t, a0, b0);
        gchunk(0, t, idx4, oA, oB, op2);
        if (have) ldg2(nxp, 1, t, a1, b1);
        gchunk(1, t, idx4, oA, oB, op2);
        if (have) { sts2(oC, 0, t, a0, b0); ldg2(nxp, 2, t, a0, b0); }
        gchunk(2, t, idx4, oA, oB, op2);
        if (have) { sts2(oC, 1, t, a1, b1); ldg2(nxp, 3, t, a1, b1); }
        gchunk(3, t, idx4, oA, oB, op2);
        if (have) {   // L2 prefetch of next plane's h1 (consumed after sync)
            const char* pf = reinterpret_cast<const char*>(nx + HALF);
            asm volatile("prefetch.global.L2 [%0];" ::
                         "l"(pf + (size_t)t * 128));
            asm volatile("prefetch.global.L2 [%0];" ::
                         "l"(pf + (size_t)(t + TPB) * 128));
        }
        gchunk(4, t, idx4, oA, oB, op2);
        if (have) sts2(oC, 2, t, a0, b0);
        gchunk(5, t, idx4, oA, oB, op2);
        if (have) sts2(oC, 3, t, a1, b1);
        gchunk(6, t, idx4, oA, oB, op2);
        gchunk(7, t, idx4, oA, oB, op2);

        if (!have) break;
        __syncthreads();   // gather done (A,B reusable); C fully written

        // ---- fill next plane's h1 -> freed A (L2 hit after prefetch) ----
        fill_half(oA, reinterpret_cast<const float4*>(nx + HALF), t);
        __syncthreads();

        // rotate: new h0 = C, new h1 = A (just filled), free = old B
        const unsigned tB = oB;
        oB = oA; oA = oC; oC = tB;
        p = pn;
    }
}

// ---------------------------------------------------------------------------
// Launch
// ---------------------------------------------------------------------------
extern "C" void kernel_launch(void* const* d_in, const int* in_sizes, int n_in,
                              void* d_out, int out_size) {
    const float*    x    = (const float*)d_in[0];
    const uint32_t* gidx = (const uint32_t*)d_in[1];
    float*          out  = (float*)d_out;

    const int planes = in_sizes[0] / NPIX;              // 16*64 = 1024
    const int smem   = 3 * HALF * (int)sizeof(__half);  // 192 KB

    // Immediate (non-stream) API, idempotent -> capture-safe.
    cudaFuncSetAttribute(pool_kernel,
                         cudaFuncAttributeMaxDynamicSharedMemorySize, smem);

    cvt_idx_kernel<<<NPIX / 8 / 256, 256>>>(gidx);   // 8 entries/thread
    pool_kernel<<<NSM, TPB, smem>>>(x, out, planes);
}

// round 16
// speedup vs baseline: 1.0952x; 1.0952x over previous
#include <cuda_runtime.h>
#include <cuda_fp16.h>
#include <cstdint>

// Problem constants
#define NPIX     65536      // 256*256
#define NOUT     16384      // 128*128
#define HALF     32768      // pixels per half-plane
#define TPB      1024
#define NSM      148

// L2-resident compressed index table (4 x uint16 per output = 128 KB)
__device__ uint16_t g_idx16[NOUT * 4];

// ---------------------------------------------------------------------------
// Pass 0: compress gather_idx (int64 OR int32, autodetected) -> uint16.
// Vectorized: each thread converts 8 entries. gather_idx is a permutation of
// [0,65536): among 8 sampled entries at most one is zero, so "first 8 odd
// u32 words all zero" <=> int64 layout.
// ---------------------------------------------------------------------------
__global__ void cvt_idx_kernel(const uint32_t* __restrict__ src) {
    const uint4* s4 = reinterpret_cast<const uint4*>(src);
    const uint4 w0 = __ldg(&s4[0]);
    const uint4 w1 = __ldg(&s4[1]);
    const uint4 w2 = __ldg(&s4[2]);
    const uint4 w3 = __ldg(&s4[3]);
    const bool is64 = (w0.y | w0.w | w1.y | w1.w | w2.y | w2.w | w3.y | w3.w) == 0u;

    const int t = blockIdx.x * blockDim.x + threadIdx.x;   // 0 .. 8191
    uint32_t v[8];
    if (is64) {
#pragma unroll
        for (int j = 0; j < 4; j++) {
            const uint4 u = __ldg(&s4[t * 4 + j]);   // two int64 entries
            v[2 * j]     = u.x;
            v[2 * j + 1] = u.z;
        }
    } else {
#pragma unroll
        for (int j = 0; j < 2; j++) {
            const uint4 u = __ldg(&s4[t * 2 + j]);   // four int32 entries
            v[4 * j]     = u.x;
            v[4 * j + 1] = u.y;
            v[4 * j + 2] = u.z;
            v[4 * j + 3] = u.w;
        }
    }
    uint4 o;
    o.x = (v[0] & 0xFFFFu) | (v[1] << 16);
    o.y = (v[2] & 0xFFFFu) | (v[3] << 16);
    o.z = (v[4] & 0xFFFFu) | (v[5] << 16);
    o.w = (v[6] & 0xFFFFu) | (v[7] << 16);
    reinterpret_cast<uint4*>(g_idx16)[t] = o;
}

// ---------------------------------------------------------------------------
// Persistent ring kernel (3 x 64KB fp16 half-plane buffers, 192 KB smem).
// R14 champion, byte-identical: 16 small gather chunks (one output each,
// uint2 idx load, scalar STG) with the next-plane h0 fill software-pipelined
// through them (LDG group i at chunk 2i, cvt+STS at chunk 2i+2).
// ---------------------------------------------------------------------------
extern __shared__ __half sh[];   // 3 * HALF halves = 192 KB dynamic

__device__ __forceinline__ void gchunk(int k, int t,
                                       const uint2* __restrict__ idx2,
                                       unsigned oA, unsigned oB,
                                       float* __restrict__ op) {
    const int o = t + k * TPB;
    const uint2 q = __ldg(&idx2[o]);
    const unsigned i0 = q.x & 0xFFFFu, i1 = q.x >> 16;
    const unsigned i2 = q.y & 0xFFFFu, i3 = q.y >> 16;
    const __half a = sh[((i0 & 0x8000u) ? oB : oA) + (i0 & 0x7FFFu)];
    const __half b = sh[((i1 & 0x8000u) ? oB : oA) + (i1 & 0x7FFFu)];
    const __half c = sh[((i2 & 0x8000u) ? oB : oA) + (i2 & 0x7FFFu)];
    const __half d = sh[((i3 & 0x8000u) ? oB : oA) + (i3 & 0x7FFFu)];
    __stcs(&op[o], __half2float(__hmax(__hmax(a, b), __hmax(c, d))));
}

__device__ __forceinline__ void ldg2(const float4* __restrict__ src, int i,
                                     int t, float4& a, float4& b) {
    const int q = t + i * TPB;                    // uint4 dst index 0..4095
    a = __ldcs(&src[2 * q]);
    b = __ldcs(&src[2 * q + 1]);
}

__device__ __forceinline__ void sts2(unsigned ofs, int i, int t,
                                     const float4& a, const float4& b) {
    const __half2 h0 = __floats2half2_rn(a.x, a.y);
    const __half2 h1 = __floats2half2_rn(a.z, a.w);
    const __half2 h2 = __floats2half2_rn(b.x, b.y);
    const __half2 h3 = __floats2half2_rn(b.z, b.w);
    uint4 u;
    u.x = *reinterpret_cast<const unsigned*>(&h0);
    u.y = *reinterpret_cast<const unsigned*>(&h1);
    u.z = *reinterpret_cast<const unsigned*>(&h2);
    u.w = *reinterpret_cast<const unsigned*>(&h3);
    reinterpret_cast<uint4*>(sh + ofs)[t + i * TPB] = u;
}

// Plain coalesced half-buffer fill (prologue + L2-hit h1 fills).
__device__ __forceinline__ void fill_half(unsigned ofs,
                                          const float4* __restrict__ src,
                                          int t) {
#pragma unroll
    for (int i = 0; i < 4; i++) {
        float4 a, b;
        ldg2(src, i, t, a, b);
        sts2(ofs, i, t, a, b);
    }
}

__global__ void __launch_bounds__(TPB, 1)
pool_kernel(const float* __restrict__ x, float* __restrict__ out, int planes) {
    const int t = threadIdx.x;
    int p = blockIdx.x;

    const uint2* __restrict__ idx2 =
        reinterpret_cast<const uint2*>(g_idx16);  // one uint2 = one output

    unsigned oA = 0, oB = HALF, oC = 2 * HALF;    // ring offsets (half units)

    // Prologue: fill h0 -> A, h1 -> B of the first plane.
    {
        const float4* xp = reinterpret_cast<const float4*>(x + (size_t)p * NPIX);
        fill_half(oA, xp, t);
        fill_half(oB, xp + HALF / 4, t);
    }
    __syncthreads();

    while (true) {
        const int pn = p + (int)gridDim.x;
        const bool have = pn < planes;
        const float* nx = x + (size_t)pn * NPIX;
        const float4* nxp = reinterpret_cast<const float4*>(nx);
        float* __restrict__ op = out + (size_t)p * NOUT;

        float4 a0, b0, a1, b1;

        // ---- gather p, with next-plane h0 fill pipelined through it ----
        if (have) ldg2(nxp, 0, t, a0, b0);
        gchunk(0, t, idx2, oA, oB, op);
        if (have) ldg2(nxp, 1, t, a1, b1);
        gchunk(1, t, idx2, oA, oB, op);
        gchunk(2, t, idx2, oA, oB, op);
        if (have) { sts2(oC, 0, t, a0, b0); ldg2(nxp, 2, t, a0, b0); }
        gchunk(3, t, idx2, oA, oB, op);
        gchunk(4, t, idx2, oA, oB, op);
        if (have) { sts2(oC, 1, t, a1, b1); ldg2(nxp, 3, t, a1, b1); }
        gchunk(5, t, idx2, oA, oB, op);
        if (have) {   // L2 prefetch of next plane's h1 (consumed after sync)
            const char* pf = reinterpret_cast<const char*>(nx + HALF);
            asm volatile("prefetch.global.L2 [%0];" ::
                         "l"(pf + (size_t)t * 128));
            asm volatile("prefetch.global.L2 [%0];" ::
                         "l"(pf + (size_t)(t + TPB) * 128));
        }
        gchunk(6, t, idx2, oA, oB, op);
        if (have) sts2(oC, 2, t, a0, b0);
        gchunk(7, t, idx2, oA, oB, op);
        gchunk(8, t, idx2, oA, oB, op);
        if (have) sts2(oC, 3, t, a1, b1);
#pragma unroll
        for (int k = 9; k < 16; k++) gchunk(k, t, idx2, oA, oB, op);

        if (!have) break;
        __syncthreads();   // gather done (A,B reusable); C fully written

        // ---- fill next plane's h1 -> freed A (L2 hit after prefetch) ----
        fill_half(oA, reinterpret_cast<const float4*>(nx + HALF), t);
        __syncthreads();

        // rotate: new h0 = C, new h1 = A (just filled), free = old B
        const unsigned tB = oB;
        oB = oA; oA = oC; oC = tB;
        p = pn;
    }
}

// ---------------------------------------------------------------------------
// Launch
// ---------------------------------------------------------------------------
extern "C" void kernel_launch(void* const* d_in, const int* in_sizes, int n_in,
                              void* d_out, int out_size) {
    const float*    x    = (const float*)d_in[0];
    const uint32_t* gidx = (const uint32_t*)d_in[1];
    float*          out  = (float*)d_out;

    const int planes = in_sizes[0] / NPIX;              // 16*64 = 1024
    const int smem   = 3 * HALF * (int)sizeof(__half);  // 192 KB

    // Immediate (non-stream) API, idempotent -> capture-safe.
    cudaFuncSetAttribute(pool_kernel,
                         cudaFuncAttributeMaxDynamicSharedMemorySize, smem);

    cvt_idx_kernel<<<NPIX / 8 / 256, 256>>>(gidx);   // 8 entries/thread
    pool_kernel<<<NSM, TPB, smem>>>(x, out, planes);
}

// round 17
// speedup vs baseline: 1.1066x; 1.0105x over previous
#include <cuda_runtime.h>
#include <cuda_fp16.h>
#include <cstdint>

// Problem constants
#define NPIX     65536      // 256*256
#define NOUT     16384      // 128*128
#define HALF     32768      // pixels per half-plane
#define TPB      1024
#define NSM      148

// L2-resident compressed index table (4 x uint16 per output = 128 KB)
__device__ uint16_t g_idx16[NOUT * 4];

// ---------------------------------------------------------------------------
// Pass 0: compress gather_idx (int64 OR int32, autodetected) -> uint16.
// Vectorized: each thread converts 8 entries. gather_idx is a permutation of
// [0,65536): among 8 sampled entries at most one is zero, so "first 8 odd
// u32 words all zero" <=> int64 layout.
// ---------------------------------------------------------------------------
__global__ void cvt_idx_kernel(const uint32_t* __restrict__ src) {
    const uint4* s4 = reinterpret_cast<const uint4*>(src);
    const uint4 w0 = __ldg(&s4[0]);
    const uint4 w1 = __ldg(&s4[1]);
    const uint4 w2 = __ldg(&s4[2]);
    const uint4 w3 = __ldg(&s4[3]);
    const bool is64 = (w0.y | w0.w | w1.y | w1.w | w2.y | w2.w | w3.y | w3.w) == 0u;

    const int t = blockIdx.x * blockDim.x + threadIdx.x;   // 0 .. 8191
    uint32_t v[8];
    if (is64) {
#pragma unroll
        for (int j = 0; j < 4; j++) {
            const uint4 u = __ldg(&s4[t * 4 + j]);   // two int64 entries
            v[2 * j]     = u.x;
            v[2 * j + 1] = u.z;
        }
    } else {
#pragma unroll
        for (int j = 0; j < 2; j++) {
            const uint4 u = __ldg(&s4[t * 2 + j]);   // four int32 entries
            v[4 * j]     = u.x;
            v[4 * j + 1] = u.y;
            v[4 * j + 2] = u.z;
            v[4 * j + 3] = u.w;
        }
    }
    uint4 o;
    o.x = (v[0] & 0xFFFFu) | (v[1] << 16);
    o.y = (v[2] & 0xFFFFu) | (v[3] << 16);
    o.z = (v[4] & 0xFFFFu) | (v[5] << 16);
    o.w = (v[6] & 0xFFFFu) | (v[7] << 16);
    reinterpret_cast<uint4*>(g_idx16)[t] = o;
}

// ---------------------------------------------------------------------------
// Persistent ring kernel (3 x 64KB fp16 half-plane buffers, 192 KB smem).
// R14/R16 champion + h1 pipelining: after the h0 staging registers die
// (chunks 7-8), they are recycled at chunks 9/12 to carry h1 groups 0-1 of
// the next plane across the barrier, halving the serial h1-fill segment.
// ---------------------------------------------------------------------------
extern __shared__ __half sh[];   // 3 * HALF halves = 192 KB dynamic

__device__ __forceinline__ void gchunk(int k, int t,
                                       const uint2* __restrict__ idx2,
                                       unsigned oA, unsigned oB,
                                       float* __restrict__ op) {
    const int o = t + k * TPB;
    const uint2 q = __ldg(&idx2[o]);
    const unsigned i0 = q.x & 0xFFFFu, i1 = q.x >> 16;
    const unsigned i2 = q.y & 0xFFFFu, i3 = q.y >> 16;
    const __half a = sh[((i0 & 0x8000u) ? oB : oA) + (i0 & 0x7FFFu)];
    const __half b = sh[((i1 & 0x8000u) ? oB : oA) + (i1 & 0x7FFFu)];
    const __half c = sh[((i2 & 0x8000u) ? oB : oA) + (i2 & 0x7FFFu)];
    const __half d = sh[((i3 & 0x8000u) ? oB : oA) + (i3 & 0x7FFFu)];
    __stcs(&op[o], __half2float(__hmax(__hmax(a, b), __hmax(c, d))));
}

__device__ __forceinline__ void ldg2(const float4* __restrict__ src, int i,
                                     int t, float4& a, float4& b) {
    const int q = t + i * TPB;                    // uint4 dst index 0..4095
    a = __ldcs(&src[2 * q]);
    b = __ldcs(&src[2 * q + 1]);
}

__device__ __forceinline__ void sts2(unsigned ofs, int i, int t,
                                     const float4& a, const float4& b) {
    const __half2 h0 = __floats2half2_rn(a.x, a.y);
    const __half2 h1 = __floats2half2_rn(a.z, a.w);
    const __half2 h2 = __floats2half2_rn(b.x, b.y);
    const __half2 h3 = __floats2half2_rn(b.z, b.w);
    uint4 u;
    u.x = *reinterpret_cast<const unsigned*>(&h0);
    u.y = *reinterpret_cast<const unsigned*>(&h1);
    u.z = *reinterpret_cast<const unsigned*>(&h2);
    u.w = *reinterpret_cast<const unsigned*>(&h3);
    reinterpret_cast<uint4*>(sh + ofs)[t + i * TPB] = u;
}

// Plain coalesced half-buffer fill (prologue only).
__device__ __forceinline__ void fill_half(unsigned ofs,
                                          const float4* __restrict__ src,
                                          int t) {
#pragma unroll
    for (int i = 0; i < 4; i++) {
        float4 a, b;
        ldg2(src, i, t, a, b);
        sts2(ofs, i, t, a, b);
    }
}

__global__ void __launch_bounds__(TPB, 1)
pool_kernel(const float* __restrict__ x, float* __restrict__ out, int planes) {
    const int t = threadIdx.x;
    int p = blockIdx.x;

    const uint2* __restrict__ idx2 =
        reinterpret_cast<const uint2*>(g_idx16);  // one uint2 = one output

    unsigned oA = 0, oB = HALF, oC = 2 * HALF;    // ring offsets (half units)

    // Prologue: fill h0 -> A, h1 -> B of the first plane.
    {
        const float4* xp = reinterpret_cast<const float4*>(x + (size_t)p * NPIX);
        fill_half(oA, xp, t);
        fill_half(oB, xp + HALF / 4, t);
    }
    __syncthreads();

    while (true) {
        const int pn = p + (int)gridDim.x;
        const bool have = pn < planes;
        const float* nx = x + (size_t)pn * NPIX;
        const float4* nxp  = reinterpret_cast<const float4*>(nx);
        const float4* nxp1 = reinterpret_cast<const float4*>(nx + HALF);
        float* __restrict__ op = out + (size_t)p * NOUT;

        float4 a0, b0, a1, b1;

        // ---- gather p; next-plane h0 fill + h1 reg-pipeline threaded in ----
        if (have) ldg2(nxp, 0, t, a0, b0);
        gchunk(0, t, idx2, oA, oB, op);
        if (have) ldg2(nxp, 1, t, a1, b1);
        gchunk(1, t, idx2, oA, oB, op);
        gchunk(2, t, idx2, oA, oB, op);
        if (have) { sts2(oC, 0, t, a0, b0); ldg2(nxp, 2, t, a0, b0); }
        gchunk(3, t, idx2, oA, oB, op);
        if (have) {   // L2 prefetch of next plane's h1 (early: feeds chunk 9+)
            const char* pf = reinterpret_cast<const char*>(nx + HALF);
            asm volatile("prefetch.global.L2 [%0];" ::
                         "l"(pf + (size_t)t * 128));
            asm volatile("prefetch.global.L2 [%0];" ::
                         "l"(pf + (size_t)(t + TPB) * 128));
        }
        gchunk(4, t, idx2, oA, oB, op);
        if (have) { sts2(oC, 1, t, a1, b1); ldg2(nxp, 3, t, a1, b1); }
        gchunk(5, t, idx2, oA, oB, op);
        gchunk(6, t, idx2, oA, oB, op);
        if (have) sts2(oC, 2, t, a0, b0);
        gchunk(7, t, idx2, oA, oB, op);
        gchunk(8, t, idx2, oA, oB, op);
        if (have) sts2(oC, 3, t, a1, b1);
        gchunk(9, t, idx2, oA, oB, op);
        if (have) ldg2(nxp1, 0, t, a0, b0);   // h1 group 0 -> recycled regs
        gchunk(10, t, idx2, oA, oB, op);
        gchunk(11, t, idx2, oA, oB, op);
        if (have) ldg2(nxp1, 1, t, a1, b1);   // h1 group 1 -> recycled regs
        gchunk(12, t, idx2, oA, oB, op);
        gchunk(13, t, idx2, oA, oB, op);
        gchunk(14, t, idx2, oA, oB, op);
        gchunk(15, t, idx2, oA, oB, op);

        if (!have) break;
        __syncthreads();   // gather done (A,B reusable); C fully written

        // ---- h1 -> freed A: groups 0-1 from registers, 2-3 from L2 ----
        sts2(oA, 0, t, a0, b0);
        sts2(oA, 1, t, a1, b1);
        ldg2(nxp1, 2, t, a0, b0);
        ldg2(nxp1, 3, t, a1, b1);
        sts2(oA, 2, t, a0, b0);
        sts2(oA, 3, t, a1, b1);
        __syncthreads();

        // rotate: new h0 = C, new h1 = A (just filled), free = old B
        const unsigned tB = oB;
        oB = oA; oA = oC; oC = tB;
        p = pn;
    }
}

// ---------------------------------------------------------------------------
// Launch
// ---------------------------------------------------------------------------
extern "C" void kernel_launch(void* const* d_in, const int* in_sizes, int n_in,
                              void* d_out, int out_size) {
    const float*    x    = (const float*)d_in[0];
    const uint32_t* gidx = (const uint32_t*)d_in[1];
    float*          out  = (float*)d_out;

    const int planes = in_sizes[0] / NPIX;              // 16*64 = 1024
    const int smem   = 3 * HALF * (int)sizeof(__half);  // 192 KB

    // Immediate (non-stream) API, idempotent -> capture-safe.
    cudaFuncSetAttribute(pool_kernel,
                         cudaFuncAttributeMaxDynamicSharedMemorySize, smem);

    cvt_idx_kernel<<<NPIX / 8 / 256, 256>>>(gidx);   // 8 entries/thread
    pool_kernel<<<NSM, TPB, smem>>>(x, out, planes);
}